// round 6
// baseline (speedup 1.0000x reference)
#include <cuda_runtime.h>

// PhotonicMesh: 512-port Clements mesh, 512 layers, 1024 batch rows.
// R6: fma.rn.f32x2 packed ACROSS BATCH ROWS (lo = row 2c, hi = row 2c+1).
// CTA = 64 threads = 2 warps (warp-half h owns ports [256h,256h+256) of the
// row pair); lane t owns ports [256h+8t, +8) of BOTH rows as u64 = (rowA,rowB).
// Packing is row-wise so per-row math is identical to the scalar kernel and
// state never needs repacking. Coefficients: 4 splatted u64 per pair (2x
// LDG.128); -st/-sin(phi) derived with LOP3 sign-XOR (ALU pipe is idle).
// Odd-layer boundary: 6 u64 shuffles + 4-u64 smem slot + 1 barrier / 2 layers.

#define N_PORT  512
#define N_LAYER 512
#define ATTEN_F 0.97723722095581054f   // sqrt(10^(-0.2/10))
#define SGN2    0x8000000080000000ULL

typedef unsigned long long u64;

// Tables: entry idx = ((l*4 + k)*2 + h)*32 + t  for pair p = 128h + 4t + k.
//   g_a = { splat(ct*ATTEN), splat(st*ATTEN) }
//   g_b = { splat(cos phi),  splat(sin phi)  }
__device__ ulonglong2 g_a[N_LAYER * 4 * 2 * 32];
__device__ ulonglong2 g_b[N_LAYER * 4 * 2 * 32];

__device__ __forceinline__ u64 splat(float v) {
    u64 d; asm("mov.b64 %0, {%1, %1};" : "=l"(d) : "f"(v)); return d;
}
__device__ __forceinline__ u64 pk(float lo, float hi) {
    u64 d; asm("mov.b64 %0, {%1, %2};" : "=l"(d) : "f"(lo), "f"(hi)); return d;
}
__device__ __forceinline__ void upk(u64 v, float& lo, float& hi) {
    asm("mov.b64 {%0, %1}, %2;" : "=f"(lo), "=f"(hi) : "l"(v));
}
__device__ __forceinline__ u64 fma2(u64 a, u64 b, u64 c) {
    u64 d; asm("fma.rn.f32x2 %0, %1, %2, %3;" : "=l"(d) : "l"(a), "l"(b), "l"(c));
    return d;
}
__device__ __forceinline__ u64 mul2(u64 a, u64 b) {
    u64 d; asm("mul.rn.f32x2 %0, %1, %2;" : "=l"(d) : "l"(a), "l"(b));
    return d;
}

__global__ void pm_coef_kernel(const float* __restrict__ thetas,
                               const float* __restrict__ phis,
                               const int*   __restrict__ mzi_idx) {
    int l   = blockIdx.x;
    int tid = threadIdx.x;            // 256
    int t = tid & 31;
    int h = (tid >> 5) & 1;
    int k = tid >> 6;                 // 0..3
    int p = 128 * h + 4 * t + k;
    bool odd = (l & 1) != 0;
    float ct = 1.f, st = 0.f, cp = 1.f, sp = 0.f;   // identity
    bool valid = odd ? (p < 255) : true;            // odd layers: 255 pairs
    if (valid) {
        int u = odd ? (2 * p + 1) : (2 * p);        // upper port of pair
        int m = mzi_idx[l * N_PORT + u];
        float s_, c_;
        sincosf(thetas[m], &s_, &c_);
        ct = c_ * ATTEN_F;  st = s_ * ATTEN_F;
        sincosf(phis[m], &s_, &c_);
        cp = c_;  sp = s_;
    }
    int idx = ((l * 4 + k) * 2 + h) * 32 + t;
    g_a[idx] = make_ulonglong2(splat(ct), splat(st));
    g_b[idx] = make_ulonglong2(splat(cp), splat(sp));
}

struct Grp { u64 ct, st, er, ei; };

__device__ __forceinline__ void load_layer(Grp g[4], int l, int h, int lane) {
    #pragma unroll
    for (int k = 0; k < 4; k++) {
        int idx = ((l * 4 + k) * 2 + h) * 32 + lane;
        ulonglong2 a = __ldg(&g_a[idx]);
        ulonglong2 b = __ldg(&g_b[idx]);
        g[k].ct = a.x;  g[k].st = a.y;
        g[k].er = b.x;  g[k].ei = b.y;
    }
}

// Packed butterfly (same MZI applied to both rows):
//   u = ct*xi + st*xj ; xj' = ct*xj - st*xi ; xi' = e^{i phi} * u
__device__ __forceinline__ void bfly2(u64& Ri, u64& Ii, u64& Rj, u64& Ij,
                                      const Grp& c) {
    u64 nst = c.st ^ SGN2;
    u64 nei = c.ei ^ SGN2;
    u64 ur = fma2(c.ct, Ri, mul2(c.st, Rj));
    u64 ui = fma2(c.ct, Ii, mul2(c.st, Ij));
    u64 vr = fma2(c.ct, Rj, mul2(nst, Ri));
    u64 vi = fma2(c.ct, Ij, mul2(nst, Ii));
    Ri = fma2(c.er, ur, mul2(nei, ui));
    Ii = fma2(c.er, ui, mul2(c.ei, ur));
    Rj = vr;  Ij = vi;
}

__global__ __launch_bounds__(64)
void pm_mesh_kernel(const float* __restrict__ x, float* __restrict__ out) {
    // boundary exchange: [parity][h0 R7, h0 I7, h1 R0, h1 I0]
    __shared__ u64 bnd[2][4];

    const int lane = threadIdx.x & 31;
    const int h    = threadIdx.x >> 5;    // warp-half: 0 = ports 0..255
    const int rA   = blockIdx.x * 2;      // row pair (rA, rA+1)

    u64 R[8], I[8];   // packed (rowA, rowB); lane owns ports 256h+8*lane..+8

    // ---- load input (real), imag = 0 ----
    {
        const float4* x4 = reinterpret_cast<const float4*>(x);
        size_t oa = (size_t)rA * (N_PORT / 4) + h * 64 + lane * 2;
        size_t ob = oa + (N_PORT / 4);
        float4 a0 = x4[oa], a1 = x4[oa + 1];
        float4 b0 = x4[ob], b1 = x4[ob + 1];
        R[0] = pk(a0.x, b0.x); R[1] = pk(a0.y, b0.y);
        R[2] = pk(a0.z, b0.z); R[3] = pk(a0.w, b0.w);
        R[4] = pk(a1.x, b1.x); R[5] = pk(a1.y, b1.y);
        R[6] = pk(a1.z, b1.z); R[7] = pk(a1.w, b1.w);
        #pragma unroll
        for (int m = 0; m < 8; m++) I[m] = 0ull;
    }

    Grp A[4], B[4];
    ulonglong2 cx = make_ulonglong2(splat(1.f), 0ull);   // h1-lane0 cross coef
    load_layer(A, 0, h, lane);

    #pragma unroll 1
    for (int l = 0; l < N_LAYER; l += 2) {
        // prefetch odd layer l+1
        load_layer(B, l + 1, h, lane);
        // h1 lane0 needs pair 127's (ct,st): table slot k=3,h=0,t=31
        if (h == 1 && lane == 0)
            cx = __ldg(&g_a[(((l + 1) * 4 + 3) * 2 + 0) * 32 + 31]);

        // ---- EVEN layer l: pairs (R0,R1)(R2,R3)(R4,R5)(R6,R7), lane-local ----
        #pragma unroll
        for (int k = 0; k < 4; k++)
            bfly2(R[2 * k], I[2 * k], R[2 * k + 1], I[2 * k + 1], A[k]);

        // publish warp-pair boundary values (post-even snapshots)
        const int par = (l >> 1) & 1;
        if (h == 0 && lane == 31) { bnd[par][0] = R[7]; bnd[par][1] = I[7]; }
        if (h == 1 && lane == 0)  { bnd[par][2] = R[0]; bnd[par][3] = I[0]; }

        // prefetch even layer l+2 (in flight across the barrier)
        int ln = (l + 2 < N_LAYER) ? (l + 2) : 0;
        load_layer(A, ln, h, lane);

        __syncthreads();

        // ---- ODD layer l+1 ----
        // pre-update snapshots (64-bit shuffles)
        u64 nR0 = __shfl_down_sync(0xffffffffu, R[0], 1);  // next lane port0
        u64 nI0 = __shfl_down_sync(0xffffffffu, I[0], 1);
        u64 pR7 = __shfl_up_sync  (0xffffffffu, R[7], 1);  // prev lane port7
        u64 pI7 = __shfl_up_sync  (0xffffffffu, I[7], 1);
        u64 ctp = __shfl_up_sync  (0xffffffffu, B[3].ct, 1);
        u64 stp = __shfl_up_sync  (0xffffffffu, B[3].st, 1);
        if (h == 0 && lane == 31) {              // partner = port 256 (warp 1)
            nR0 = bnd[par][2]; nI0 = bnd[par][3];
        }
        if (h == 1 && lane == 0) {               // partner = port 255 (warp 0)
            pR7 = bnd[par][0]; pI7 = bnd[par][1];
            ctp = cx.x; stp = cx.y;
        }
        if (h == 0 && lane == 0) {               // global port 0 passthrough
            ctp = splat(1.f); stp = 0ull;
        }

        // local pairs (R1,R2)(R3,R4)(R5,R6)
        bfly2(R[1], I[1], R[2], I[2], B[0]);
        bfly2(R[3], I[3], R[4], I[4], B[1]);
        bfly2(R[5], I[5], R[6], I[6], B[2]);

        // cross pair upper port (port 8t+7): phase applies; identity at port 511
        {
            u64 nei = B[3].ei ^ SGN2;
            u64 ur = fma2(B[3].ct, R[7], mul2(B[3].st, nR0));
            u64 ui = fma2(B[3].ct, I[7], mul2(B[3].st, nI0));
            R[7] = fma2(B[3].er, ur, mul2(nei, ui));
            I[7] = fma2(B[3].er, ui, mul2(B[3].ei, ur));
        }
        // cross pair lower port (port 8t): real coefficients
        {
            u64 nstp = stp ^ SGN2;
            R[0] = fma2(ctp, R[0], mul2(nstp, pR7));
            I[0] = fma2(ctp, I[0], mul2(nstp, pI7));
        }
    }

    // ---- square-law detection + store (both rows) ----
    {
        float pa[8], pb[8];
        #pragma unroll
        for (int m = 0; m < 8; m++) {
            float ra, rb, ia, ib;
            upk(R[m], ra, rb);  upk(I[m], ia, ib);
            pa[m] = ra * ra + ia * ia;
            pb[m] = rb * rb + ib * ib;
        }
        float4* o4 = reinterpret_cast<float4*>(out);
        size_t oa = (size_t)rA * (N_PORT / 4) + h * 64 + lane * 2;
        size_t ob = oa + (N_PORT / 4);
        o4[oa]     = make_float4(pa[0], pa[1], pa[2], pa[3]);
        o4[oa + 1] = make_float4(pa[4], pa[5], pa[6], pa[7]);
        o4[ob]     = make_float4(pb[0], pb[1], pb[2], pb[3]);
        o4[ob + 1] = make_float4(pb[4], pb[5], pb[6], pb[7]);
    }
}

extern "C" void kernel_launch(void* const* d_in, const int* in_sizes, int n_in,
                              void* d_out, int out_size) {
    const float* x       = (const float*)d_in[0];
    const float* thetas  = (const float*)d_in[1];
    const float* phis    = (const float*)d_in[2];
    // d_in[3] = partner (unused: structure is static)
    const int*   mzi_idx = (const int*)d_in[4];
    // d_in[5] = role (unused: structure is static)
    float* out = (float*)d_out;

    pm_coef_kernel<<<N_LAYER, 256>>>(thetas, phis, mzi_idx);
    // 512 CTAs x 2 warps; CTA c = rows (2c, 2c+1), warp h = port half
    pm_mesh_kernel<<<512, 64>>>(x, out);
}

// round 7
// speedup vs baseline: 1.6583x; 1.6583x over previous
#include <cuda_runtime.h>

// PhotonicMesh: 512-port Clements mesh, 512 layers, 1024 batch rows.
// R7: identical per-warp algorithm to R2 (best: 123.5us), but launched as
// 1024 single-warp CTAs so the CTA scheduler spreads the 1024 independent
// row-warps across ALL ~148-152 SMs instead of 8 warps x 128 SMs.
// R2 was ~80% of the FFMA-rt floor at 128 SMs; using every SM lowers the
// floor by ~14%. Warp body: lane t owns ports [16t,16t+16); even layers
// lane-local, odd layers 4 shuffles + 1 cross pair; ping-pong coef prefetch.

#define N_PORT  512
#define N_LAYER 512
#define N_PAIR  256
#define ATTEN_F 0.97723722095581054f   // sqrt(10^(-0.2/10))

// Coefficient table, layout: [(l*8 + k)*32 + lane] where pair p = 8*lane + k.
// Per-k load across a warp is a fully coalesced 512B read.
__device__ float4 g_coef[N_LAYER * N_PAIR];

__global__ void pm_coef_kernel(const float* __restrict__ thetas,
                               const float* __restrict__ phis,
                               const int*   __restrict__ mzi_idx) {
    int l = blockIdx.x;      // layer
    int p = threadIdx.x;     // pair index within layer
    float4 c = make_float4(1.0f, 0.0f, 1.0f, 0.0f);  // identity (unused slots)
    bool odd = (l & 1) != 0;
    bool valid = (!odd) || (p < N_PAIR - 1);         // odd layers have 255 pairs
    if (valid) {
        int i = odd ? (2 * p + 1) : (2 * p);         // upper port of the pair
        int m = mzi_idx[l * N_PORT + i];
        float st, ct, sp, cp;
        sincosf(thetas[m], &st, &ct);
        sincosf(phis[m],   &sp, &cp);
        c = make_float4(ct * ATTEN_F, st * ATTEN_F, cp, sp);
    }
    g_coef[(l * 8 + (p & 7)) * 32 + (p >> 3)] = c;
}

// new_i = e^{i phi}(ct*x_i + st*x_j) ; new_j = ct*x_j - st*x_i
__device__ __forceinline__ void butterfly(float2& xi, float2& xj, float4 c) {
    float ct = c.x, st = c.y, er = c.z, ei = c.w;
    float ur = ct * xi.x + st * xj.x;
    float ui = ct * xi.y + st * xj.y;
    float vr = ct * xj.x - st * xi.x;
    float vi = ct * xj.y - st * xi.y;
    xi.x = er * ur - ei * ui;
    xi.y = er * ui + ei * ur;
    xj.x = vr;
    xj.y = vi;
}

// Load coefficients for even layer l (c[0..7]) and odd layer l+1 (c[8..15]).
// c[16] = cross-pair coefficient owned by lane-1 (pair 8*(lane-1)+7 of layer
// l+1), read directly from the table instead of shuffling.
__device__ __forceinline__ void load_coefs(float4* c, int l, int lane) {
    const float4* ce = g_coef + (size_t)l * N_PAIR;
    const float4* co = g_coef + (size_t)(l + 1) * N_PAIR;
    #pragma unroll
    for (int k = 0; k < 8; k++) c[k]     = __ldg(&ce[k * 32 + lane]);
    #pragma unroll
    for (int k = 0; k < 8; k++) c[k + 8] = __ldg(&co[k * 32 + lane]);
    int lm = (lane > 0) ? (lane - 1) : 0;   // lane0 value unused (port 0 pass)
    c[16] = __ldg(&co[7 * 32 + lm]);
}

// EVEN layer: pairs (16*lane+2k, 16*lane+2k+1), all lane-local.
__device__ __forceinline__ void do_even(float2* s, const float4* c) {
    #pragma unroll
    for (int k = 0; k < 8; k++)
        butterfly(s[2 * k], s[2 * k + 1], c[k]);
}

// ODD layer: local pairs (2k+1, 2k+2) for k=0..6; cross pair
// (16*lane+15, 16*(lane+1)) via shuffles; ports 0 and 511 pass through.
// c[0..7] = this lane's pairs; cx = lane-1's pair-7 coefficient.
__device__ __forceinline__ void do_odd(float2* s, const float4* c, float4 cx,
                                       int lane) {
    // snapshot neighbor values BEFORE any update this layer
    float xjr = __shfl_down_sync(0xffffffffu, s[0].x, 1);   // (lane+1).port0
    float xji = __shfl_down_sync(0xffffffffu, s[0].y, 1);
    float xir = __shfl_up_sync(0xffffffffu, s[15].x, 1);    // (lane-1).port15
    float xii = __shfl_up_sync(0xffffffffu, s[15].y, 1);
    #pragma unroll
    for (int k = 0; k < 7; k++)
        butterfly(s[2 * k + 1], s[2 * k + 2], c[k]);
    if (lane < 31) {  // upper port of cross pair: gets the phase
        float ct = c[7].x, st = c[7].y, er = c[7].z, ei = c[7].w;
        float ur = ct * s[15].x + st * xjr;
        float ui = ct * s[15].y + st * xji;
        s[15].x = er * ur - ei * ui;
        s[15].y = er * ui + ei * ur;
    }
    if (lane > 0) {   // lower port of cross pair: real coefficients
        float2 x0 = s[0];
        s[0].x = cx.x * x0.x - cx.y * xir;
        s[0].y = cx.x * x0.y - cx.y * xii;
    }
}

__global__ __launch_bounds__(32)
void pm_mesh_kernel(const float* __restrict__ x, float* __restrict__ out) {
    const int lane = threadIdx.x & 31;
    const int row  = blockIdx.x;          // one warp-CTA per batch row

    float2 s[16];             // complex state: lane owns ports 16*lane..16*lane+15

    // ---- load input (real), imag = 0 ----
    const float4* x4 = reinterpret_cast<const float4*>(x);
    #pragma unroll
    for (int v = 0; v < 4; v++) {
        float4 q = x4[(size_t)row * (N_PORT / 4) + lane * 4 + v];
        s[4 * v + 0] = make_float2(q.x, 0.f);
        s[4 * v + 1] = make_float2(q.y, 0.f);
        s[4 * v + 2] = make_float2(q.z, 0.f);
        s[4 * v + 3] = make_float2(q.w, 0.f);
    }

    // ---- software-pipelined propagation: ping-pong coefficient buffers ----
    float4 cA[17], cB[17];
    load_coefs(cA, 0, lane);

    // Each outer iteration processes 4 layers (A then B) while prefetching.
    #pragma unroll 1
    for (int l = 0; l < N_LAYER; l += 4) {
        int ln1 = l + 2;  if (ln1 > N_LAYER - 2) ln1 = 0;   // clamp (result unused)
        load_coefs(cB, ln1, lane);
        do_even(s, cA);
        do_odd (s, cA + 8, cA[16], lane);

        int ln2 = l + 4;  if (ln2 > N_LAYER - 2) ln2 = 0;   // clamp (result unused)
        load_coefs(cA, ln2, lane);
        do_even(s, cB);
        do_odd (s, cB + 8, cB[16], lane);
    }

    // ---- square-law detection + store ----
    float4* o4 = reinterpret_cast<float4*>(out);
    #pragma unroll
    for (int v = 0; v < 4; v++) {
        float4 q;
        q.x = s[4 * v + 0].x * s[4 * v + 0].x + s[4 * v + 0].y * s[4 * v + 0].y;
        q.y = s[4 * v + 1].x * s[4 * v + 1].x + s[4 * v + 1].y * s[4 * v + 1].y;
        q.z = s[4 * v + 2].x * s[4 * v + 2].x + s[4 * v + 2].y * s[4 * v + 2].y;
        q.w = s[4 * v + 3].x * s[4 * v + 3].x + s[4 * v + 3].y * s[4 * v + 3].y;
        o4[(size_t)row * (N_PORT / 4) + lane * 4 + v] = q;
    }
}

extern "C" void kernel_launch(void* const* d_in, const int* in_sizes, int n_in,
                              void* d_out, int out_size) {
    const float* x       = (const float*)d_in[0];
    const float* thetas  = (const float*)d_in[1];
    const float* phis    = (const float*)d_in[2];
    // d_in[3] = partner (unused: structure is static)
    const int*   mzi_idx = (const int*)d_in[4];
    // d_in[5] = role (unused: structure is static)
    float* out = (float*)d_out;

    pm_coef_kernel<<<N_LAYER, N_PAIR>>>(thetas, phis, mzi_idx);
    // 1024 single-warp CTAs: spread across ALL SMs (~7 per SM on 148+ SMs)
    pm_mesh_kernel<<<1024, 32>>>(x, out);
}